// round 5
// baseline (speedup 1.0000x reference)
#include <cuda_runtime.h>
#include <cstdint>

// Embedding gather: out[r, :] = weight[ids[r], :]
// weight: [50257, 1024] fp32, ids: [32768] int32 (JAX demotes int64->int32),
// out: [32768, 1024] fp32
//
// One CTA per output row. 256 threads x float4 = 4KB per row.
// Weight loads use default caching (partial L2 residency of the 205MB table);
// stores use .cs streaming hint so the 128MB of write-once output data does
// not evict gathered weight rows from L2.

#define DIM 1024
#define THREADS 256   // DIM/4 float4 per row

__global__ __launch_bounds__(THREADS, 8)
void embed_gather_kernel(const float4* __restrict__ weight,
                         const int* __restrict__ ids,
                         float4* __restrict__ out,
                         int n_rows)
{
    int row = blockIdx.x;
    if (row >= n_rows) return;

    int idx = ids[row];  // broadcast load, L1 hit for all lanes

    const float4* src = weight + (size_t)idx * (DIM / 4);
    float4* dst       = out    + (size_t)row * (DIM / 4);

    float4 v = src[threadIdx.x];

    // streaming store: keep L2 for the gathered weight table
    asm volatile("st.global.cs.v4.f32 [%0], {%1, %2, %3, %4};"
                 :: "l"(dst + threadIdx.x),
                    "f"(v.x), "f"(v.y), "f"(v.z), "f"(v.w)
                 : "memory");
}

extern "C" void kernel_launch(void* const* d_in, const int* in_sizes, int n_in,
                              void* d_out, int out_size)
{
    // Identify inputs by element count rather than trusting order:
    //   weight: 50257*1024 = 51463168 elements
    //   ids:    16*2048    = 32768 elements
    const void* p0 = d_in[0];
    const void* p1 = d_in[1];
    const float4* weight;
    const int* ids;
    int n_rows;

    if (in_sizes[0] > in_sizes[1]) {
        weight = (const float4*)p0;
        ids    = (const int*)p1;
        n_rows = in_sizes[1];
    } else {
        weight = (const float4*)p1;
        ids    = (const int*)p0;
        n_rows = in_sizes[0];
    }

    embed_gather_kernel<<<n_rows, THREADS>>>(weight, ids, (float4*)d_out, n_rows);
}

// round 6
// speedup vs baseline: 1.1583x; 1.1583x over previous
#include <cuda_runtime.h>
#include <cstdint>

// Embedding gather: out[r, :] = weight[ids[r], :]
// weight: [50257, 1024] fp32, ids: [32768] int32, out: [32768, 1024] fp32
//
// MLP-optimized: 8 rows per CTA, 256 threads. Each thread owns one float4
// column slot across all 8 rows:
//   - 8 independent index loads (tiny, L2/L1-resident) -> one wait
//   - 8 independent 16B gather loads issued back-to-back (MLP=8)
//   - 8 streaming stores (.cs) so the write-once output doesn't evict the
//     hot weight rows from L2 (touched subset ~94MB of 126MB L2).

#define DIM4 256          // DIM/4 float4 per row
#define THREADS 256
#define ROWS_PER_CTA 8

__global__ __launch_bounds__(THREADS)
void embed_gather_kernel(const float4* __restrict__ weight,
                         const int* __restrict__ ids,
                         float4* __restrict__ out,
                         int n_rows)
{
    const int tid  = threadIdx.x;
    const int base = blockIdx.x * ROWS_PER_CTA;

    // 8 independent broadcast index loads
    int idx[ROWS_PER_CTA];
#pragma unroll
    for (int r = 0; r < ROWS_PER_CTA; r++)
        idx[r] = ids[base + r];

    // 8 independent gathers — front-batched by ptxas -> MLP=8 per thread
    float4 v[ROWS_PER_CTA];
#pragma unroll
    for (int r = 0; r < ROWS_PER_CTA; r++)
        v[r] = weight[(size_t)idx[r] * DIM4 + tid];

    // 8 streaming stores
#pragma unroll
    for (int r = 0; r < ROWS_PER_CTA; r++) {
        float4* dst = out + (size_t)(base + r) * DIM4 + tid;
        asm volatile("st.global.cs.v4.f32 [%0], {%1, %2, %3, %4};"
                     :: "l"(dst),
                        "f"(v[r].x), "f"(v[r].y), "f"(v[r].z), "f"(v[r].w)
                     : "memory");
    }
}

extern "C" void kernel_launch(void* const* d_in, const int* in_sizes, int n_in,
                              void* d_out, int out_size)
{
    // Identify inputs by element count:
    //   weight: 50257*1024 = 51463168 elements; ids: 32768 elements
    const float4* weight;
    const int* ids;
    int n_rows;

    if (in_sizes[0] > in_sizes[1]) {
        weight = (const float4*)d_in[0];
        ids    = (const int*)d_in[1];
        n_rows = in_sizes[1];
    } else {
        weight = (const float4*)d_in[1];
        ids    = (const int*)d_in[0];
        n_rows = in_sizes[0];
    }

    int n_blocks = n_rows / ROWS_PER_CTA;  // 32768/8 = 4096, exact
    embed_gather_kernel<<<n_blocks, THREADS>>>(weight, ids, (float4*)d_out, n_rows);
}

// round 7
// speedup vs baseline: 1.1977x; 1.0340x over previous
#include <cuda_runtime.h>
#include <cstdint>

// Embedding gather: out[r, :] = weight[ids[r], :]
// weight: [50257, 1024] fp32, ids: [32768] int32, out: [32768, 1024] fp32
//
// MLP-forced variant: 8 rows per CTA, 256 threads, one float4 column slot
// per thread. The 8 gather loads are opaque asm volatile LDG.128 issued
// back-to-back BEFORE any store, so ptxas cannot re-interleave them to save
// registers (R6 showed regs=32 -> MLP_eff ~3-4 instead of 8).
// __launch_bounds__(256, 4) raises the register cap to 64 so all 8 results
// stay live: 32 warps/SM x 8 outstanding gathers = 256 in-flight loads/SM.
// Stores use .cs streaming so the write-once output doesn't evict the hot
// weight subset (~94MB) from L2.

#define DIM4 256          // DIM/4 float4 per row
#define THREADS 256
#define ROWS_PER_CTA 8

__global__ __launch_bounds__(THREADS, 4)
void embed_gather_kernel(const float4* __restrict__ weight,
                         const int* __restrict__ ids,
                         float4* __restrict__ out,
                         int n_rows)
{
    const int tid  = threadIdx.x;
    const int base = blockIdx.x * ROWS_PER_CTA;

    // 8 independent broadcast index loads (L1/L2-hot, one wait)
    int idx[ROWS_PER_CTA];
#pragma unroll
    for (int r = 0; r < ROWS_PER_CTA; r++)
        idx[r] = ids[base + r];

    // 8 gather addresses
    const float4* src[ROWS_PER_CTA];
#pragma unroll
    for (int r = 0; r < ROWS_PER_CTA; r++)
        src[r] = weight + (size_t)idx[r] * DIM4 + tid;

    // 8 opaque LDG.128 issued back-to-back: true MLP=8
    float v[ROWS_PER_CTA][4];
#pragma unroll
    for (int r = 0; r < ROWS_PER_CTA; r++) {
        asm volatile("ld.global.v4.f32 {%0, %1, %2, %3}, [%4];"
                     : "=f"(v[r][0]), "=f"(v[r][1]), "=f"(v[r][2]), "=f"(v[r][3])
                     : "l"(src[r]));
    }

    // 8 streaming stores; each waits only on its own result
#pragma unroll
    for (int r = 0; r < ROWS_PER_CTA; r++) {
        float4* dst = out + (size_t)(base + r) * DIM4 + tid;
        asm volatile("st.global.cs.v4.f32 [%0], {%1, %2, %3, %4};"
                     :: "l"(dst),
                        "f"(v[r][0]), "f"(v[r][1]), "f"(v[r][2]), "f"(v[r][3])
                     : "memory");
    }
}

extern "C" void kernel_launch(void* const* d_in, const int* in_sizes, int n_in,
                              void* d_out, int out_size)
{
    // Identify inputs by element count:
    //   weight: 50257*1024 = 51463168 elements; ids: 32768 elements
    const float4* weight;
    const int* ids;
    int n_rows;

    if (in_sizes[0] > in_sizes[1]) {
        weight = (const float4*)d_in[0];
        ids    = (const int*)d_in[1];
        n_rows = in_sizes[1];
    } else {
        weight = (const float4*)d_in[1];
        ids    = (const int*)d_in[0];
        n_rows = in_sizes[0];
    }

    int n_blocks = n_rows / ROWS_PER_CTA;  // 32768/8 = 4096, exact
    embed_gather_kernel<<<n_blocks, THREADS>>>(weight, ids, (float4*)d_out, n_rows);
}